// round 14
// baseline (speedup 1.0000x reference)
#include <cuda_runtime.h>
#include <cuda_fp16.h>
#include <cstdint>
#include <cstddef>

#define N_SENT 32768
#define EMSIZE 2048
#define NCLASS 128
#define NCOLS  384   // 3 taps * 128
#define TAPS   3

// ---------------- scratch (allocation-free) ----------------
__device__ __half g_Yh[(size_t)N_SENT * NCOLS];            // stage-1 per-tap GEMM out, fp16
__device__ __half g_Gh[(size_t)N_SENT * NCOLS];            // stage-2 GEMM out, fp16
__device__ __half g_Hh[(size_t)N_SENT * NCLASS];           // tanh hidden, fp16
__device__ __half g_W1h[(size_t)TAPS * NCLASS * EMSIZE];   // [tap][c][e] K-major fp16
__device__ __half g_W2h[(size_t)TAPS * NCLASS * NCLASS];   // [tap][c][k] K-major fp16
__device__ float  g_sink[64];

// ---------------- PTX helpers ----------------
__device__ __forceinline__ uint32_t smem_u32(const void* p) {
    uint32_t a;
    asm("{ .reg .u64 t; cvta.to.shared.u64 t, %1; cvt.u32.u64 %0, t; }" : "=r"(a) : "l"(p));
    return a;
}
__device__ __forceinline__ void cp_async16(uint32_t saddr, const void* g) {
    asm volatile("cp.async.ca.shared.global [%0], [%1], 16;" :: "r"(saddr), "l"(g));
}
__device__ __forceinline__ void cp_commit() {
    asm volatile("cp.async.commit_group;" ::: "memory");
}
template<int n> __device__ __forceinline__ void cp_wait() {
    asm volatile("cp.async.wait_group %0;" :: "n"(n) : "memory");
}
__device__ __forceinline__ void ldsm4(uint32_t r[4], uint32_t saddr) {
    asm volatile("ldmatrix.sync.aligned.m8n8.x4.shared.b16 {%0,%1,%2,%3}, [%4];"
                 : "=r"(r[0]), "=r"(r[1]), "=r"(r[2]), "=r"(r[3]) : "r"(saddr));
}
__device__ __forceinline__ void mma16816(float d[4], const uint32_t a[4], const uint32_t b[2]) {
    asm volatile(
        "mma.sync.aligned.m16n8k16.row.col.f32.f16.f16.f32 "
        "{%0,%1,%2,%3},{%4,%5,%6,%7},{%8,%9},{%0,%1,%2,%3};"
        : "+f"(d[0]), "+f"(d[1]), "+f"(d[2]), "+f"(d[3])
        : "r"(a[0]), "r"(a[1]), "r"(a[2]), "r"(a[3]), "r"(b[0]), "r"(b[1]));
}
__device__ __forceinline__ uint32_t packh2(float lo, float hi) {
    __half2 h = __floats2half2_rn(lo, hi);
    return *reinterpret_cast<uint32_t*>(&h);
}

// Swizzled 16B-chunk offset inside an N-row x 32-half (64B/row) tile.
__device__ __forceinline__ uint32_t tile_off(int row, int c) {
    return (uint32_t)(row * 64 + ((c ^ ((row >> 1) & 3)) << 4));
}

// ===================== K1: 128x128 tile, A direct-to-register =====================
// A (fp32 x) never touches smem: each thread LDG.64s its m16n8k16 fragment
// elements (lanes 0..3 cover 32 contiguous bytes -> full sectors), converts to
// half2, double-buffered across K-chunks. B: 4-stage cp.async ring, 8KB/stage.
#define S1_BYTES   8192
#define SMEM1      (S1_BYTES * 4)     // 32 KB

__global__ void __launch_bounds__(256, 2)
gemm1_kernel(const float* __restrict__ Af,
             const __half* __restrict__ Bg,
             __half* __restrict__ C,
             int K)
{
    extern __shared__ __align__(128) uint8_t dsm[];

    const int tid  = threadIdx.x;
    const int lane = tid & 31;
    const int warp = tid >> 5;
    const int wm   = warp >> 1;   // 0..3 (32 rows)
    const int wn   = warp & 1;    // 0..1 (64 cols)
    const int tap  = blockIdx.x % TAPS;
    const int m0   = (blockIdx.x / TAPS) * 128;
    const __half* Bt = Bg + (size_t)tap * 128 * K;
    const int KT = K >> 5;

    // B loader: row = tid>>2 (0..63, +64), chunk col = tid&3
    const int lrow = tid >> 2;
    const int lc   = tid & 3;
    const uint32_t soffB1 = tile_off(lrow, lc);
    const uint32_t soffB2 = soffB1 + 64 * 64;

    const uint32_t sbase = smem_u32(dsm);
    uint32_t boff[4][2];
    {
        const int brow0 = wn * 64 + (lane & 7) + 8 * (lane >> 4);
        const int bcadd = (lane >> 3) & 1;
        #pragma unroll
        for (int kk = 0; kk < 2; kk++)
            #pragma unroll
            for (int nip = 0; nip < 4; nip++)
                boff[nip][kk] = tile_off(brow0 + nip * 16, kk * 2 + bcadd);
    }

    // A fragment base pointers: rows wm*32 + mi*16 + (lane>>2) + {0,8}; col (lane&3)*2
    const int ar = lane >> 2, ac = (lane & 3) * 2;
    const float* pA[2][2];   // [mi][rq] rq: +0 / +8
    #pragma unroll
    for (int mi = 0; mi < 2; mi++) {
        pA[mi][0] = Af + (size_t)(m0 + wm * 32 + mi * 16 + ar) * K + ac;
        pA[mi][1] = pA[mi][0] + (size_t)8 * K;
    }

    float acc[2][8][4];
    #pragma unroll
    for (int mi = 0; mi < 2; mi++)
        #pragma unroll
        for (int ni = 0; ni < 8; ni++)
            #pragma unroll
            for (int q = 0; q < 4; q++) acc[mi][ni][q] = 0.f;

    uint32_t acur[2][2][4], anxt[2][2][4];   // [mi][kk][q], q: (r,k0)(r+8,k0)(r,k8)(r+8,k8)

    // load+convert A fragments for a chunk into dst
    auto loadA = [&](uint32_t dst[2][2][4], int kbase) {
        #pragma unroll
        for (int mi = 0; mi < 2; mi++)
            #pragma unroll
            for (int kk = 0; kk < 2; kk++) {
                const int o = kbase + kk * 16;
                float2 v0 = *(const float2*)(pA[mi][0] + o);
                float2 v1 = *(const float2*)(pA[mi][1] + o);
                float2 v2 = *(const float2*)(pA[mi][0] + o + 8);
                float2 v3 = *(const float2*)(pA[mi][1] + o + 8);
                dst[mi][kk][0] = packh2(v0.x, v0.y);
                dst[mi][kk][1] = packh2(v1.x, v1.y);
                dst[mi][kk][2] = packh2(v2.x, v2.y);
                dst[mi][kk][3] = packh2(v3.x, v3.y);
            }
    };

    // ---- prologue: B chunks 0,1 via cp.async; A chunk 0 -> regs ----
    #pragma unroll
    for (int s = 0; s < 2; s++) {
        const uint32_t sp = sbase + s * S1_BYTES;
        const int kb = s << 5;
        cp_async16(sp + soffB1, Bt + (size_t)lrow * K + kb + lc * 8);
        cp_async16(sp + soffB2, Bt + (size_t)(lrow + 64) * K + kb + lc * 8);
        cp_commit();
    }
    loadA(acur, 0);

    for (int kt = 0; kt < KT; kt++) {
        const uint32_t sbuf = sbase + (uint32_t)(kt & 3) * S1_BYTES;

        // prefetch B chunk kt+2 -> stage (kt+2)%4 (!= (kt-1)%4: safe pre-barrier)
        if (kt + 2 < KT) {
            const int kb = (kt + 2) << 5;
            const uint32_t sp = sbase + (uint32_t)((kt + 2) & 3) * S1_BYTES;
            cp_async16(sp + soffB1, Bt + (size_t)lrow * K + kb + lc * 8);
            cp_async16(sp + soffB2, Bt + (size_t)(lrow + 64) * K + kb + lc * 8);
            cp_commit();
        }

        // LDG+convert A chunk kt+1 into anxt (independent of smem; overlaps)
        if (kt + 1 < KT) loadA(anxt, (kt + 1) << 5);

        if      (kt + 2 < KT) cp_wait<2>();
        else if (kt + 1 < KT) cp_wait<1>();
        else                  cp_wait<0>();
        __syncthreads();

        #pragma unroll
        for (int kk = 0; kk < 2; kk++) {
            uint32_t b[4][4];
            #pragma unroll
            for (int nip = 0; nip < 4; nip++) ldsm4(b[nip], sbuf + boff[nip][kk]);
            #pragma unroll
            for (int mi = 0; mi < 2; mi++)
                #pragma unroll
                for (int ni = 0; ni < 8; ni++)
                    mma16816(acc[mi][ni], acur[mi][kk], &b[ni >> 1][(ni & 1) * 2]);
        }

        // rotate A buffers
        #pragma unroll
        for (int mi = 0; mi < 2; mi++)
            #pragma unroll
            for (int kk = 0; kk < 2; kk++)
                #pragma unroll
                for (int q = 0; q < 4; q++)
                    acur[mi][kk][q] = anxt[mi][kk][q];
        // no trailing barrier (4-stage ring; next writes hit stages kt+3 only)
    }

    // epilogue: fp16 out
    const int gid = lane >> 2, tig = lane & 3;
    #pragma unroll
    for (int mi = 0; mi < 2; mi++) {
        const int r0 = m0 + wm * 32 + mi * 16 + gid;
        #pragma unroll
        for (int ni = 0; ni < 8; ni++) {
            const int col = tap * 128 + wn * 64 + ni * 8 + tig * 2;
            __half2 lo = __floats2half2_rn(acc[mi][ni][0], acc[mi][ni][1]);
            __half2 hi = __floats2half2_rn(acc[mi][ni][2], acc[mi][ni][3]);
            *(__half2*)&C[(size_t)r0 * NCOLS + col]       = lo;
            *(__half2*)&C[(size_t)(r0 + 8) * NCOLS + col] = hi;
        }
    }
}

// ===================== gemm2: short-K (K=128), R12-proven =====================
#define S2_BYTES   16384
#define SMEM2      (S2_BYTES * 4)     // 65536

__global__ void __launch_bounds__(256, 2)
gemm2_kernel(const __half* __restrict__ Ah,
             const __half* __restrict__ Bg,
             __half* __restrict__ C)
{
    extern __shared__ __align__(128) uint8_t dsm[];
    constexpr int K = NCLASS;   // 128

    const int tid  = threadIdx.x;
    const int lane = tid & 31;
    const int warp = tid >> 5;
    const int wm   = warp >> 1;
    const int wn   = warp & 1;
    const int tap  = blockIdx.x % TAPS;
    const int m0   = (blockIdx.x / TAPS) * 128;
    const __half* Bt = Bg + (size_t)tap * 128 * K;

    const int lrow = tid >> 2;
    const int lc   = tid & 3;
    const uint32_t soff1 = tile_off(lrow, lc);
    const uint32_t soff2 = soff1 + 64 * 64;

    const uint32_t sbase = smem_u32(dsm);
    uint32_t aoff[2][2], boff[4][2];
    {
        const int arow0 = wm * 32 + (lane & 7) + 8 * ((lane >> 3) & 1);
        const int acadd = lane >> 4;
        const int brow0 = wn * 64 + (lane & 7) + 8 * (lane >> 4);
        const int bcadd = (lane >> 3) & 1;
        #pragma unroll
        for (int kk = 0; kk < 2; kk++) {
            #pragma unroll
            for (int mi = 0; mi < 2; mi++)
                aoff[mi][kk] = tile_off(arow0 + mi * 16, kk * 2 + acadd);
            #pragma unroll
            for (int nip = 0; nip < 4; nip++)
                boff[nip][kk] = tile_off(brow0 + nip * 16, kk * 2 + bcadd);
        }
    }

    float acc[2][8][4];
    #pragma unroll
    for (int mi = 0; mi < 2; mi++)
        #pragma unroll
        for (int ni = 0; ni < 8; ni++)
            #pragma unroll
            for (int q = 0; q < 4; q++) acc[mi][ni][q] = 0.f;

    #pragma unroll
    for (int s = 0; s < 4; s++) {
        const uint32_t sp = sbase + s * S2_BYTES;
        const int kb = s << 5;
        cp_async16(sp + soff1, Ah + (size_t)(m0 + lrow) * K + kb + lc * 8);
        cp_async16(sp + soff2, Ah + (size_t)(m0 + lrow + 64) * K + kb + lc * 8);
        cp_async16(sp + 8192 + soff1, Bt + (size_t)lrow * K + kb + lc * 8);
        cp_async16(sp + 8192 + soff2, Bt + (size_t)(lrow + 64) * K + kb + lc * 8);
        cp_commit();
    }

    #pragma unroll
    for (int kt = 0; kt < 4; kt++) {
        if      (kt == 0) cp_wait<3>();
        else if (kt == 1) cp_wait<2>();
        else if (kt == 2) cp_wait<1>();
        else              cp_wait<0>();
        __syncthreads();

        const uint32_t sbuf = sbase + (uint32_t)kt * S2_BYTES;
        #pragma unroll
        for (int kk = 0; kk < 2; kk++) {
            uint32_t a[2][4], b[4][4];
            #pragma unroll
            for (int mi = 0; mi < 2; mi++) ldsm4(a[mi], sbuf + aoff[mi][kk]);
            #pragma unroll
            for (int nip = 0; nip < 4; nip++) ldsm4(b[nip], sbuf + 8192 + boff[nip][kk]);
            #pragma unroll
            for (int mi = 0; mi < 2; mi++)
                #pragma unroll
                for (int ni = 0; ni < 8; ni++)
                    mma16816(acc[mi][ni], a[mi], &b[ni >> 1][(ni & 1) * 2]);
        }
    }

    const int gid = lane >> 2, tig = lane & 3;
    #pragma unroll
    for (int mi = 0; mi < 2; mi++) {
        const int r0 = m0 + wm * 32 + mi * 16 + gid;
        #pragma unroll
        for (int ni = 0; ni < 8; ni++) {
            const int col = tap * 128 + wn * 64 + ni * 8 + tig * 2;
            __half2 lo = __floats2half2_rn(acc[mi][ni][0], acc[mi][ni][1]);
            __half2 hi = __floats2half2_rn(acc[mi][ni][2], acc[mi][ni][3]);
            *(__half2*)&C[(size_t)r0 * NCOLS + col]       = lo;
            *(__half2*)&C[(size_t)(r0 + 8) * NCOLS + col] = hi;
        }
    }
}

// ---------------- merged weight transpose + fp16 convert ----------------
__global__ void transpose_all_kernel(const float* __restrict__ W1, const float* __restrict__ W2,
                                     __half* __restrict__ W1h, __half* __restrict__ W2h)
{
    __shared__ float tile[32][33];
    const int z = blockIdx.z;
    const float* src; __half* dst; int E;
    if (z < 3) {
        E = EMSIZE;
        src = W1 + (size_t)z * EMSIZE * NCLASS;
        dst = W1h + (size_t)z * NCLASS * EMSIZE;
    } else {
        E = NCLASS;
        if (blockIdx.x >= NCLASS / 32) return;
        src = W2 + (size_t)(z - 3) * NCLASS * NCLASS;
        dst = W2h + (size_t)(z - 3) * NCLASS * NCLASS;
    }
    const int e0 = blockIdx.x << 5, c0 = blockIdx.y << 5;
    #pragma unroll
    for (int j = 0; j < 32; j += 8)
        tile[threadIdx.y + j][threadIdx.x] =
            src[(size_t)(e0 + threadIdx.y + j) * NCLASS + c0 + threadIdx.x];
    __syncthreads();
    #pragma unroll
    for (int j = 0; j < 32; j += 8)
        dst[(size_t)(c0 + threadIdx.y + j) * E + e0 + threadIdx.x] =
            __float2half_rn(tile[threadIdx.x][threadIdx.y + j]);
}

// ---------------- spacers (gemm1 -> ncu capture slot, launch idx 3) ----------------
__global__ void spacer_kernel(const float* __restrict__ b, float* __restrict__ sink, int off)
{
    sink[threadIdx.x + off] = b[threadIdx.x];
}

// ---------------- combine + tanh (Y fp16 in) -> fp16 H ----------------
__global__ void combine_tanh_kernel(const __half* __restrict__ Yh,
                                    const float4* __restrict__ b1_4,
                                    uint2* __restrict__ H2)
{
    int idx = blockIdx.x * blockDim.x + threadIdx.x;   // < N_SENT*32
    int p = idx >> 5, q = idx & 31;
    const __half2* y0 = (const __half2*)&Yh[(size_t)p * NCOLS + 4 * q];
    float2 s0 = __half22float2(y0[0]), s1 = __half22float2(y0[1]);
    float cnt = 1.f;
    if (p >= 1) {
        const __half2* a = (const __half2*)&Yh[(size_t)(p - 1) * NCOLS + 128 + 4 * q];
        float2 a0 = __half22float2(a[0]), a1 = __half22float2(a[1]);
        s0.x += a0.x; s0.y += a0.y; s1.x += a1.x; s1.y += a1.y; cnt = 2.f;
    }
    if (p >= 2) {
        const __half2* a = (const __half2*)&Yh[(size_t)(p - 2) * NCOLS + 256 + 4 * q];
        float2 a0 = __half22float2(a[0]), a1 = __half22float2(a[1]);
        s0.x += a0.x; s0.y += a0.y; s1.x += a1.x; s1.y += a1.y; cnt = 3.f;
    }
    float4 b = b1_4[q];
    __half2 h01 = __floats2half2_rn(tanhf(s0.x + cnt * b.x), tanhf(s0.y + cnt * b.y));
    __half2 h23 = __floats2half2_rn(tanhf(s1.x + cnt * b.z), tanhf(s1.y + cnt * b.w));
    uint2 u;
    u.x = *reinterpret_cast<uint32_t*>(&h01);
    u.y = *reinterpret_cast<uint32_t*>(&h23);
    H2[(size_t)p * 32 + q] = u;
}

// ---------------- stage-2 combine + fallback + log_softmax (warp/row) ----------------
__global__ void stage2_softmax_kernel(const __half* __restrict__ G,
                                      const __half* __restrict__ Yh,
                                      const float4* __restrict__ W2_4,
                                      const float4* __restrict__ b1_4,
                                      const float4* __restrict__ b2_4,
                                      float4* __restrict__ out4)
{
    const int warp = threadIdx.x >> 5, lane = threadIdx.x & 31;
    const int i = blockIdx.x * 8 + warp;
    float4 z;
    float4 bb = b2_4[lane];
    if (i >= 2) {
        const __half2* g0 = (const __half2*)&G[(size_t)(i - 2) * NCOLS + 4 * lane];
        const __half2* g1 = (const __half2*)&G[(size_t)(i - 1) * NCOLS + 128 + 4 * lane];
        const __half2* g2 = (const __half2*)&G[(size_t)i * NCOLS + 256 + 4 * lane];
        float2 a0 = __half22float2(g0[0]), a1 = __half22float2(g0[1]);
        float2 b0 = __half22float2(g1[0]), b1v = __half22float2(g1[1]);
        float2 c0 = __half22float2(g2[0]), c1 = __half22float2(g2[1]);
        z.x = a0.x + b0.x + c0.x + 3.f * bb.x;
        z.y = a0.y + b0.y + c0.y + 3.f * bb.y;
        z.z = a1.x + b1v.x + c1.x + 3.f * bb.z;
        z.w = a1.y + b1v.y + c1.y + 3.f * bb.w;
    } else {
        const __half2* y = (const __half2*)&Yh[(size_t)i * NCOLS + 4 * lane];
        float2 y0 = __half22float2(y[0]), y1 = __half22float2(y[1]);
        float4 b1f = b1_4[lane];
        float4 h;
        h.x = tanhf(y0.x + b1f.x); h.y = tanhf(y0.y + b1f.y);
        h.z = tanhf(y1.x + b1f.z); h.w = tanhf(y1.y + b1f.w);
        float4 acc = bb;
        for (int j = 0; j < 32; j++) {
            float hx = __shfl_sync(0xffffffffu, h.x, j);
            float hy = __shfl_sync(0xffffffffu, h.y, j);
            float hz = __shfl_sync(0xffffffffu, h.z, j);
            float hw = __shfl_sync(0xffffffffu, h.w, j);
            int k = 4 * j;
            float4 w0 = W2_4[(size_t)(k + 0) * 32 + lane];
            float4 w1 = W2_4[(size_t)(k + 1) * 32 + lane];
            float4 w2 = W2_4[(size_t)(k + 2) * 32 + lane];
            float4 w3 = W2_4[(size_t)(k + 3) * 32 + lane];
            acc.x += hx * w0.x + hy * w1.x + hz * w2.x + hw * w3.x;
            acc.y += hx * w0.y + hy * w1.y + hz * w2.y + hw * w3.y;
            acc.z += hx * w0.z + hy * w1.z + hz * w2.z + hw * w3.z;
            acc.w += hx * w0.w + hy * w1.w + hz * w2.w + hw * w3.w;
        }
        z = acc;
    }
    float m = fmaxf(fmaxf(z.x, z.y), fmaxf(z.z, z.w));
    #pragma unroll
    for (int o = 16; o > 0; o >>= 1) m = fmaxf(m, __shfl_xor_sync(0xffffffffu, m, o));
    float s = __expf(z.x - m) + __expf(z.y - m) + __expf(z.z - m) + __expf(z.w - m);
    #pragma unroll
    for (int o = 16; o > 0; o >>= 1) s += __shfl_xor_sync(0xffffffffu, s, o);
    float ls = m + __logf(s);
    out4[(size_t)i * 32 + lane] = make_float4(z.x - ls, z.y - ls, z.z - ls, z.w - ls);
}

// ---------------- launch ----------------
extern "C" void kernel_launch(void* const* d_in, const int* in_sizes, int n_in,
                              void* d_out, int out_size)
{
    const float* x  = (const float*)d_in[0];
    const float* W1 = (const float*)d_in[1];
    const float* b1 = (const float*)d_in[2];
    const float* W2 = (const float*)d_in[3];
    const float* b2 = (const float*)d_in[4];
    float* out = (float*)d_out;

    __half *Yh, *Gh, *Hh, *W1h, *W2h; float* sink;
    cudaGetSymbolAddress((void**)&Yh,   g_Yh);
    cudaGetSymbolAddress((void**)&Gh,   g_Gh);
    cudaGetSymbolAddress((void**)&Hh,   g_Hh);
    cudaGetSymbolAddress((void**)&W1h,  g_W1h);
    cudaGetSymbolAddress((void**)&W2h,  g_W2h);
    cudaGetSymbolAddress((void**)&sink, g_sink);

    static bool attr_done = false;
    if (!attr_done) {
        cudaFuncSetAttribute((const void*)gemm1_kernel,
                             cudaFuncAttributeMaxDynamicSharedMemorySize, SMEM1);
        cudaFuncSetAttribute((const void*)gemm2_kernel,
                             cudaFuncAttributeMaxDynamicSharedMemorySize, SMEM2);
        attr_done = true;
    }

    // 0: weight transposes
    transpose_all_kernel<<<dim3(EMSIZE / 32, NCLASS / 32, 6), dim3(32, 8)>>>(W1, W2, W1h, W2h);

    // 1,2: spacers (put gemm1 at the ncu capture slot, launch idx 3)
    spacer_kernel<<<1, 32>>>(b1, sink, 0);
    spacer_kernel<<<1, 32>>>(b2, sink, 32);

    // 3: K1  Y = x @ W1 per tap (fp16 out), A direct-to-register, grid 768
    gemm1_kernel<<<(N_SENT / 128) * TAPS, 256, SMEM1>>>(x, W1h, Yh, EMSIZE);

    // 4: H = tanh(shifted sum + cnt*b1) -> fp16
    combine_tanh_kernel<<<(N_SENT * 32) / 256, 256>>>(
        Yh, (const float4*)b1, (uint2*)Hh);

    // 5: G = H @ W2 (fp16 out)
    gemm2_kernel<<<(N_SENT / 128) * TAPS, 256, SMEM2>>>(Hh, W2h, Gh);

    // 6: Z combine + fallback + log_softmax
    stage2_softmax_kernel<<<N_SENT / 8, 256>>>(
        Gh, Yh, (const float4*)W2,
        (const float4*)b1, (const float4*)b2, (float4*)out);
}

// round 15
// speedup vs baseline: 1.3199x; 1.3199x over previous
#include <cuda_runtime.h>
#include <cuda_fp16.h>
#include <cstdint>
#include <cstddef>

#define N_SENT 32768
#define EMSIZE 2048
#define NCLASS 128
#define NCOLS  384   // 3 taps * 128
#define TAPS   3

// ---------------- scratch (allocation-free) ----------------
__device__ __half g_Yh[(size_t)N_SENT * NCOLS];            // stage-1 per-tap GEMM out, fp16
__device__ __half g_Gh[(size_t)N_SENT * NCOLS];            // stage-2 GEMM out, fp16
__device__ __half g_W1h[(size_t)TAPS * NCLASS * EMSIZE];   // [tap][c][e] K-major fp16
__device__ __half g_W2h[(size_t)TAPS * NCLASS * NCLASS];   // [tap][c][k] K-major fp16
__device__ float  g_sink[64];

// ---------------- PTX helpers ----------------
__device__ __forceinline__ uint32_t smem_u32(const void* p) {
    uint32_t a;
    asm("{ .reg .u64 t; cvta.to.shared.u64 t, %1; cvt.u32.u64 %0, t; }" : "=r"(a) : "l"(p));
    return a;
}
__device__ __forceinline__ void cp_async16(uint32_t saddr, const void* g) {
    asm volatile("cp.async.ca.shared.global [%0], [%1], 16;" :: "r"(saddr), "l"(g));
}
__device__ __forceinline__ void cp_commit() {
    asm volatile("cp.async.commit_group;" ::: "memory");
}
template<int n> __device__ __forceinline__ void cp_wait() {
    asm volatile("cp.async.wait_group %0;" :: "n"(n) : "memory");
}
__device__ __forceinline__ void ldsm4(uint32_t r[4], uint32_t saddr) {
    asm volatile("ldmatrix.sync.aligned.m8n8.x4.shared.b16 {%0,%1,%2,%3}, [%4];"
                 : "=r"(r[0]), "=r"(r[1]), "=r"(r[2]), "=r"(r[3]) : "r"(saddr));
}
__device__ __forceinline__ void mma16816(float d[4], const uint32_t a[4], const uint32_t b[2]) {
    asm volatile(
        "mma.sync.aligned.m16n8k16.row.col.f32.f16.f16.f32 "
        "{%0,%1,%2,%3},{%4,%5,%6,%7},{%8,%9},{%0,%1,%2,%3};"
        : "+f"(d[0]), "+f"(d[1]), "+f"(d[2]), "+f"(d[3])
        : "r"(a[0]), "r"(a[1]), "r"(a[2]), "r"(a[3]), "r"(b[0]), "r"(b[1]));
}

// Swizzled 16B-chunk offset inside an N-row x 32-half (64B/row) tile.
__device__ __forceinline__ uint32_t tile_off(int row, int c) {
    return (uint32_t)(row * 64 + ((c ^ ((row >> 1) & 3)) << 4));
}

// ===================== K1: byte-identical to R12 (best measured) =====================
#define S1_BYTES   16384
#define SMEM1      (S1_BYTES * 4)     // 64 KB

__global__ void __launch_bounds__(256, 2)
gemm1_kernel(const float* __restrict__ Af,
             const __half* __restrict__ Bg,
             __half* __restrict__ C,
             int K)
{
    extern __shared__ __align__(128) uint8_t dsm[];

    const int tid  = threadIdx.x;
    const int lane = tid & 31;
    const int warp = tid >> 5;
    const int wm   = warp >> 1;
    const int wn   = warp & 1;
    const int tap  = blockIdx.x % TAPS;
    const int m0   = (blockIdx.x / TAPS) * 128;
    const __half* Bt = Bg + (size_t)tap * 128 * K;
    const int KT = K >> 5;

    const int lrow = tid >> 2;
    const int lc   = tid & 3;
    const uint32_t soff1 = tile_off(lrow, lc);
    const uint32_t soff2 = soff1 + 64 * 64;

    const uint32_t sbase = smem_u32(dsm);
    uint32_t aoff[2][2], boff[4][2];
    {
        const int arow0 = wm * 32 + (lane & 7) + 8 * ((lane >> 3) & 1);
        const int acadd = lane >> 4;
        const int brow0 = wn * 64 + (lane & 7) + 8 * (lane >> 4);
        const int bcadd = (lane >> 3) & 1;
        #pragma unroll
        for (int kk = 0; kk < 2; kk++) {
            #pragma unroll
            for (int mi = 0; mi < 2; mi++)
                aoff[mi][kk] = tile_off(arow0 + mi * 16, kk * 2 + acadd);
            #pragma unroll
            for (int nip = 0; nip < 4; nip++)
                boff[nip][kk] = tile_off(brow0 + nip * 16, kk * 2 + bcadd);
        }
    }

    float acc[2][8][4];
    #pragma unroll
    for (int mi = 0; mi < 2; mi++)
        #pragma unroll
        for (int ni = 0; ni < 8; ni++)
            #pragma unroll
            for (int q = 0; q < 4; q++) acc[mi][ni][q] = 0.f;

    __half2 st[8];

    #pragma unroll
    for (int s = 0; s < 2; s++) {
        const uint32_t sp = sbase + s * S1_BYTES;
        const int kb = s << 5;
        cp_async16(sp + 8192 + soff1, Bt + (size_t)lrow * K + kb + lc * 8);
        cp_async16(sp + 8192 + soff2, Bt + (size_t)(lrow + 64) * K + kb + lc * 8);
        cp_commit();
    }
    {
        const float* p1 = Af + (size_t)(m0 + lrow) * K + lc * 8;
        const float* p2 = Af + (size_t)(m0 + lrow + 64) * K + lc * 8;
        float4 v0 = *(const float4*)p1, v1 = *(const float4*)(p1 + 4);
        float4 w0 = *(const float4*)p2, w1 = *(const float4*)(p2 + 4);
        st[0] = __floats2half2_rn(v0.x, v0.y); st[1] = __floats2half2_rn(v0.z, v0.w);
        st[2] = __floats2half2_rn(v1.x, v1.y); st[3] = __floats2half2_rn(v1.z, v1.w);
        st[4] = __floats2half2_rn(w0.x, w0.y); st[5] = __floats2half2_rn(w0.z, w0.w);
        st[6] = __floats2half2_rn(w1.x, w1.y); st[7] = __floats2half2_rn(w1.z, w1.w);
    }

    for (int kt = 0; kt < KT; kt++) {
        const uint32_t sbuf = sbase + (uint32_t)(kt & 3) * S1_BYTES;

        *(uint4*)(dsm + (kt & 3) * S1_BYTES + soff1) = *(uint4*)(&st[0]);
        *(uint4*)(dsm + (kt & 3) * S1_BYTES + soff2) = *(uint4*)(&st[4]);

        if (kt + 2 < KT) {
            const int kb = (kt + 2) << 5;
            const uint32_t sp = sbase + (uint32_t)((kt + 2) & 3) * S1_BYTES;
            cp_async16(sp + 8192 + soff1, Bt + (size_t)lrow * K + kb + lc * 8);
            cp_async16(sp + 8192 + soff2, Bt + (size_t)(lrow + 64) * K + kb + lc * 8);
            cp_commit();
        }

        if (kt + 1 < KT) {
            const int kb = (kt + 1) << 5;
            const float* p1 = Af + (size_t)(m0 + lrow) * K + kb + lc * 8;
            const float* p2 = Af + (size_t)(m0 + lrow + 64) * K + kb + lc * 8;
            float4 v0 = *(const float4*)p1, v1 = *(const float4*)(p1 + 4);
            float4 w0 = *(const float4*)p2, w1 = *(const float4*)(p2 + 4);
            st[0] = __floats2half2_rn(v0.x, v0.y); st[1] = __floats2half2_rn(v0.z, v0.w);
            st[2] = __floats2half2_rn(v1.x, v1.y); st[3] = __floats2half2_rn(v1.z, v1.w);
            st[4] = __floats2half2_rn(w0.x, w0.y); st[5] = __floats2half2_rn(w0.z, w0.w);
            st[6] = __floats2half2_rn(w1.x, w1.y); st[7] = __floats2half2_rn(w1.z, w1.w);
        }

        if      (kt + 2 < KT) cp_wait<2>();
        else if (kt + 1 < KT) cp_wait<1>();
        else                  cp_wait<0>();
        __syncthreads();

        #pragma unroll
        for (int kk = 0; kk < 2; kk++) {
            uint32_t a[2][4], b[4][4];
            #pragma unroll
            for (int mi = 0; mi < 2; mi++) ldsm4(a[mi], sbuf + aoff[mi][kk]);
            #pragma unroll
            for (int nip = 0; nip < 4; nip++) ldsm4(b[nip], sbuf + 8192 + boff[nip][kk]);
            #pragma unroll
            for (int mi = 0; mi < 2; mi++)
                #pragma unroll
                for (int ni = 0; ni < 8; ni++)
                    mma16816(acc[mi][ni], a[mi], &b[ni >> 1][(ni & 1) * 2]);
        }
    }

    const int gid = lane >> 2, tig = lane & 3;
    #pragma unroll
    for (int mi = 0; mi < 2; mi++) {
        const int r0 = m0 + wm * 32 + mi * 16 + gid;
        #pragma unroll
        for (int ni = 0; ni < 8; ni++) {
            const int col = tap * 128 + wn * 64 + ni * 8 + tig * 2;
            __half2 lo = __floats2half2_rn(acc[mi][ni][0], acc[mi][ni][1]);
            __half2 hi = __floats2half2_rn(acc[mi][ni][2], acc[mi][ni][3]);
            *(__half2*)&C[(size_t)r0 * NCOLS + col]       = lo;
            *(__half2*)&C[(size_t)(r0 + 8) * NCOLS + col] = hi;
        }
    }
}

// ===================== gemm2_fused: combine+tanh (H in smem) + 3-tap GEMM =====================
// One CTA per 128-row block (grid 256). Phase 0 builds the 128x128 H tile in smem
// (4 swizzled 8KB sub-tiles, identical layout to R12's A stages). Then 12 K-chunks
// (tap = ch>>2), B via depth-3 cp.async ring; epilogue per tap writes G fp16.
#define H_OFF   0
#define B_OFF   32768
#define SMEM2   65536   // H 32KB + B ring 32KB

__global__ void __launch_bounds__(256, 2)
gemm2_fused(const __half* __restrict__ Yh,
            const __half* __restrict__ W2h,
            const float* __restrict__ b1,
            __half* __restrict__ G)
{
    extern __shared__ __align__(128) uint8_t dsm[];
    const int tid  = threadIdx.x;
    const int lane = tid & 31;
    const int warp = tid >> 5;
    const int wm   = warp >> 1;
    const int wn   = warp & 1;
    const int m0   = blockIdx.x * 128;
    const uint32_t sbase = smem_u32(dsm);

    // B loader
    const int lrow = tid >> 2, lc = tid & 3;
    const uint32_t sB1 = tile_off(lrow, lc);
    const uint32_t sB2 = sB1 + 4096;

    // fragment offsets (within an 8KB sub-tile / stage)
    uint32_t aoff[2][2], boff[4][2];
    {
        const int arow0 = wm * 32 + (lane & 7) + 8 * ((lane >> 3) & 1);
        const int acadd = lane >> 4;
        const int brow0 = wn * 64 + (lane & 7) + 8 * (lane >> 4);
        const int bcadd = (lane >> 3) & 1;
        #pragma unroll
        for (int kk = 0; kk < 2; kk++) {
            #pragma unroll
            for (int mi = 0; mi < 2; mi++)
                aoff[mi][kk] = tile_off(arow0 + mi * 16, kk * 2 + acadd);
            #pragma unroll
            for (int nip = 0; nip < 4; nip++)
                boff[nip][kk] = tile_off(brow0 + nip * 16, kk * 2 + bcadd);
        }
    }

    // prologue: prefetch B chunks 0,1,2 (all tap 0)
    #pragma unroll
    for (int ch = 0; ch < 3; ch++) {
        const uint32_t sp = sbase + B_OFF + (uint32_t)ch * 8192;
        cp_async16(sp + sB1, W2h + (size_t)lrow * 128 + ch * 32 + lc * 8);
        cp_async16(sp + sB2, W2h + (size_t)(lrow + 64) * 128 + ch * 32 + lc * 8);
        cp_commit();
    }

    // phase 0: H tile = tanh(shifted Y sum + cnt*b1) -> smem (overlaps B prefetch)
    {
        const int cg = tid & 63;          // half2 column 0..63
        const int rb = tid >> 6;          // 0..3
        const float2 b1v = *(const float2*)(b1 + 2 * cg);
        const int c = 2 * cg;
        const int kc = c >> 5, w = c & 31;
        const uint32_t cbase = (uint32_t)(kc * 8192) + (uint32_t)((w & 7) * 2);
        #pragma unroll 4
        for (int j = 0; j < 32; j++) {
            const int r = rb * 32 + j;
            const int p = m0 + r;
            float2 s = __half22float2(*(const __half2*)&Yh[(size_t)p * NCOLS + c]);
            float cnt = 1.f;
            if (p >= 1) {
                float2 a = __half22float2(*(const __half2*)&Yh[(size_t)(p - 1) * NCOLS + 128 + c]);
                s.x += a.x; s.y += a.y; cnt = 2.f;
            }
            if (p >= 2) {
                float2 a = __half22float2(*(const __half2*)&Yh[(size_t)(p - 2) * NCOLS + 256 + c]);
                s.x += a.x; s.y += a.y; cnt = 3.f;
            }
            __half2 h = __floats2half2_rn(tanhf(s.x + cnt * b1v.x), tanhf(s.y + cnt * b1v.y));
            *(__half2*)(dsm + cbase + tile_off(r, w >> 3)) = h;
        }
    }
    __syncthreads();   // H tile complete (B waits handled per-chunk below)

    float acc[2][8][4];
    #pragma unroll
    for (int mi = 0; mi < 2; mi++)
        #pragma unroll
        for (int ni = 0; ni < 8; ni++)
            #pragma unroll
            for (int q = 0; q < 4; q++) acc[mi][ni][q] = 0.f;

    const int gid = lane >> 2, tig = lane & 3;

    for (int ch = 0; ch < 12; ch++) {
        // wait ledger: groups issued = 3 + ch; need chunk ch done.
        if      (ch <= 9)  cp_wait<2>();
        else if (ch == 10) cp_wait<1>();
        else               cp_wait<0>();
        __syncthreads();

        // prefetch chunk ch+3 -> stage (ch+3)%4 == (ch-1)%4 (dead after this barrier)
        if (ch + 3 < 12) {
            const int nc = ch + 3, ntap = nc >> 2, nk2 = nc & 3;
            const __half* Bt = W2h + (size_t)ntap * NCLASS * NCLASS;
            const uint32_t sp = sbase + B_OFF + (uint32_t)(nc & 3) * 8192;
            cp_async16(sp + sB1, Bt + (size_t)lrow * 128 + nk2 * 32 + lc * 8);
            cp_async16(sp + sB2, Bt + (size_t)(lrow + 64) * 128 + nk2 * 32 + lc * 8);
            cp_commit();
        }

        const uint32_t hbase = sbase + (uint32_t)(ch & 3) * 8192;           // H sub-tile k2
        const uint32_t bbase = sbase + B_OFF + (uint32_t)(ch & 3) * 8192;   // B stage
        #pragma unroll
        for (int kk = 0; kk < 2; kk++) {
            uint32_t a[2][4], b[4][4];
            #pragma unroll
            for (int mi = 0; mi < 2; mi++) ldsm4(a[mi], hbase + aoff[mi][kk]);
            #pragma unroll
            for (int nip = 0; nip < 4; nip++) ldsm4(b[nip], bbase + boff[nip][kk]);
            #pragma unroll
            for (int mi = 0; mi < 2; mi++)
                #pragma unroll
                for (int ni = 0; ni < 8; ni++)
                    mma16816(acc[mi][ni], a[mi], &b[ni >> 1][(ni & 1) * 2]);
        }

        // tap boundary: write this tap's output, reset acc
        if ((ch & 3) == 3) {
            const int tap = ch >> 2;
            #pragma unroll
            for (int mi = 0; mi < 2; mi++) {
                const int r0 = m0 + wm * 32 + mi * 16 + gid;
                #pragma unroll
                for (int ni = 0; ni < 8; ni++) {
                    const int col = tap * 128 + wn * 64 + ni * 8 + tig * 2;
                    __half2 lo = __floats2half2_rn(acc[mi][ni][0], acc[mi][ni][1]);
                    __half2 hi = __floats2half2_rn(acc[mi][ni][2], acc[mi][ni][3]);
                    *(__half2*)&G[(size_t)r0 * NCOLS + col]       = lo;
                    *(__half2*)&G[(size_t)(r0 + 8) * NCOLS + col] = hi;
                    #pragma unroll
                    for (int q = 0; q < 4; q++) acc[mi][ni][q] = 0.f;
                }
            }
        }
    }
}

// ---------------- merged weight transpose + fp16 convert ----------------
__global__ void transpose_all_kernel(const float* __restrict__ W1, const float* __restrict__ W2,
                                     __half* __restrict__ W1h, __half* __restrict__ W2h)
{
    __shared__ float tile[32][33];
    const int z = blockIdx.z;
    const float* src; __half* dst; int E;
    if (z < 3) {
        E = EMSIZE;
        src = W1 + (size_t)z * EMSIZE * NCLASS;
        dst = W1h + (size_t)z * NCLASS * EMSIZE;
    } else {
        E = NCLASS;
        if (blockIdx.x >= NCLASS / 32) return;
        src = W2 + (size_t)(z - 3) * NCLASS * NCLASS;
        dst = W2h + (size_t)(z - 3) * NCLASS * NCLASS;
    }
    const int e0 = blockIdx.x << 5, c0 = blockIdx.y << 5;
    #pragma unroll
    for (int j = 0; j < 32; j += 8)
        tile[threadIdx.y + j][threadIdx.x] =
            src[(size_t)(e0 + threadIdx.y + j) * NCLASS + c0 + threadIdx.x];
    __syncthreads();
    #pragma unroll
    for (int j = 0; j < 32; j += 8)
        dst[(size_t)(c0 + threadIdx.y + j) * E + e0 + threadIdx.x] =
            __float2half_rn(tile[threadIdx.x][threadIdx.y + j]);
}

// ---------------- spacer (keeps gemm2_fused at ncu slot 3) ----------------
__global__ void spacer_kernel(const float* __restrict__ b, float* __restrict__ sink)
{
    sink[threadIdx.x] = b[threadIdx.x];
}

// ---------------- stage-2 combine + fallback + log_softmax (warp/row) ----------------
__global__ void stage2_softmax_kernel(const __half* __restrict__ G,
                                      const __half* __restrict__ Yh,
                                      const float4* __restrict__ W2_4,
                                      const float4* __restrict__ b1_4,
                                      const float4* __restrict__ b2_4,
                                      float4* __restrict__ out4)
{
    const int warp = threadIdx.x >> 5, lane = threadIdx.x & 31;
    const int i = blockIdx.x * 8 + warp;
    float4 z;
    float4 bb = b2_4[lane];
    if (i >= 2) {
        const __half2* g0 = (const __half2*)&G[(size_t)(i - 2) * NCOLS + 4 * lane];
        const __half2* g1 = (const __half2*)&G[(size_t)(i - 1) * NCOLS + 128 + 4 * lane];
        const __half2* g2 = (const __half2*)&G[(size_t)i * NCOLS + 256 + 4 * lane];
        float2 a0 = __half22float2(g0[0]), a1 = __half22float2(g0[1]);
        float2 b0 = __half22float2(g1[0]), b1v = __half22float2(g1[1]);
        float2 c0 = __half22float2(g2[0]), c1 = __half22float2(g2[1]);
        z.x = a0.x + b0.x + c0.x + 3.f * bb.x;
        z.y = a0.y + b0.y + c0.y + 3.f * bb.y;
        z.z = a1.x + b1v.x + c1.x + 3.f * bb.z;
        z.w = a1.y + b1v.y + c1.y + 3.f * bb.w;
    } else {
        const __half2* y = (const __half2*)&Yh[(size_t)i * NCOLS + 4 * lane];
        float2 y0 = __half22float2(y[0]), y1 = __half22float2(y[1]);
        float4 b1f = b1_4[lane];
        float4 h;
        h.x = tanhf(y0.x + b1f.x); h.y = tanhf(y0.y + b1f.y);
        h.z = tanhf(y1.x + b1f.z); h.w = tanhf(y1.y + b1f.w);
        float4 acc = bb;
        for (int j = 0; j < 32; j++) {
            float hx = __shfl_sync(0xffffffffu, h.x, j);
            float hy = __shfl_sync(0xffffffffu, h.y, j);
            float hz = __shfl_sync(0xffffffffu, h.z, j);
            float hw = __shfl_sync(0xffffffffu, h.w, j);
            int k = 4 * j;
            float4 w0 = W2_4[(size_t)(k + 0) * 32 + lane];
            float4 w1 = W2_4[(size_t)(k + 1) * 32 + lane];
            float4 w2 = W2_4[(size_t)(k + 2) * 32 + lane];
            float4 w3 = W2_4[(size_t)(k + 3) * 32 + lane];
            acc.x += hx * w0.x + hy * w1.x + hz * w2.x + hw * w3.x;
            acc.y += hx * w0.y + hy * w1.y + hz * w2.y + hw * w3.y;
            acc.z += hx * w0.z + hy * w1.z + hz * w2.z + hw * w3.z;
            acc.w += hx * w0.w + hy * w1.w + hz * w2.w + hw * w3.w;
        }
        z = acc;
    }
    float m = fmaxf(fmaxf(z.x, z.y), fmaxf(z.z, z.w));
    #pragma unroll
    for (int o = 16; o > 0; o >>= 1) m = fmaxf(m, __shfl_xor_sync(0xffffffffu, m, o));
    float s = __expf(z.x - m) + __expf(z.y - m) + __expf(z.z - m) + __expf(z.w - m);
    #pragma unroll
    for (int o = 16; o > 0; o >>= 1) s += __shfl_xor_sync(0xffffffffu, s, o);
    float ls = m + __logf(s);
    out4[(size_t)i * 32 + lane] = make_float4(z.x - ls, z.y - ls, z.z - ls, z.w - ls);
}

// ---------------- launch ----------------
extern "C" void kernel_launch(void* const* d_in, const int* in_sizes, int n_in,
                              void* d_out, int out_size)
{
    const float* x  = (const float*)d_in[0];
    const float* W1 = (const float*)d_in[1];
    const float* b1 = (const float*)d_in[2];
    const float* W2 = (const float*)d_in[3];
    const float* b2 = (const float*)d_in[4];
    float* out = (float*)d_out;

    __half *Yh, *Gh, *W1h, *W2h; float* sink;
    cudaGetSymbolAddress((void**)&Yh,   g_Yh);
    cudaGetSymbolAddress((void**)&Gh,   g_Gh);
    cudaGetSymbolAddress((void**)&W1h,  g_W1h);
    cudaGetSymbolAddress((void**)&W2h,  g_W2h);
    cudaGetSymbolAddress((void**)&sink, g_sink);

    static bool attr_done = false;
    if (!attr_done) {
        cudaFuncSetAttribute((const void*)gemm1_kernel,
                             cudaFuncAttributeMaxDynamicSharedMemorySize, SMEM1);
        cudaFuncSetAttribute((const void*)gemm2_fused,
                             cudaFuncAttributeMaxDynamicSharedMemorySize, SMEM2);
        attr_done = true;
    }

    // 0: weight transposes
    transpose_all_kernel<<<dim3(EMSIZE / 32, NCLASS / 32, 6), dim3(32, 8)>>>(W1, W2, W1h, W2h);

    // 1: spacer (puts gemm2_fused at ncu capture slot 3)
    spacer_kernel<<<1, 32>>>(b1, sink);

    // 2: K1  Y = x @ W1 per tap (fp16 out), R12 config, grid 768
    gemm1_kernel<<<(N_SENT / 128) * TAPS, 256, SMEM1>>>(x, W1h, Yh, EMSIZE);

    // 3: fused combine+tanh + G = H @ W2 (3 taps), grid 256  <- profiled slot
    gemm2_fused<<<N_SENT / 128, 256, SMEM2>>>(Yh, W2h, b1, Gh);

    // 4: Z combine + fallback + log_softmax
    stage2_softmax_kernel<<<N_SENT / 8, 256>>>(
        Gh, Yh, (const float4*)W2,
        (const float4*)b1, (const float4*)b2, (float4*)out);
}